// round 1
// baseline (speedup 1.0000x reference)
#include <cuda_runtime.h>
#include <cuda_bf16.h>

#define IMG_H 1080
#define IMG_W 1920
#define THR 20.0f

// Circle offsets (dy, dx) in circular (Bresenham) order — bit i of the mask.
__device__ __constant__ int c_dy[16] = { 0, 1, 2, 3, 3, 3, 2, 1, 0, -1, -2, -3, -3, -3, -2, -1};
__device__ __constant__ int c_dx[16] = {-3, -3, -2, -1, 0, 1, 2, 3, 3, 3, 2, 1, 0, -1, -2, -3};

// Host-side copies for constexpr unrolling in the fast path.
#define DY0 0
#define DX0 -3

static __device__ __forceinline__ bool run9(unsigned m) {
    // m: 16-bit circular mask. Detect any run of >=9 consecutive set bits.
    unsigned d = m * 0x10001u;   // duplicate into high half (circular wrap)
    unsigned r = d & (d >> 1);   // runs >= 2
    r &= (r >> 2);               // runs >= 4
    r &= (r >> 4);               // runs >= 8
    r &= (d >> 8);               // runs >= 9
    return (r & 0xFFFFu) != 0u;
}

__global__ __launch_bounds__(128, 4)
void fast_score_kernel(const float* __restrict__ img, float* __restrict__ out, int N)
{
    // dy, dx tables as compile-time constants for full unrolling
    const int DY[16] = { 0, 1, 2, 3, 3, 3, 2, 1, 0, -1, -2, -3, -3, -3, -2, -1};
    const int DX[16] = {-3, -3, -2, -1, 0, 1, 2, 3, 3, 3, 2, 1, 0, -1, -2, -3};

    int x0 = (blockIdx.x * blockDim.x + threadIdx.x) * 4;
    int y  = blockIdx.y;
    int n  = blockIdx.z;
    if (x0 >= IMG_W) return;

    const float* im = img + (size_t)n * IMG_H * IMG_W;
    float*       op = out + ((size_t)n * IMG_H + y) * IMG_W + x0;

    bool interior = (y >= 3) & (y <= IMG_H - 4) & (x0 >= 4) & (x0 + 7 <= IMG_W - 1);

    if (interior) {
        // Load 7 rows x 12 floats ([x0-4, x0+7]) into registers via aligned float4.
        float r[7][12];
#pragma unroll
        for (int ry = 0; ry < 7; ry++) {
            const float* p = im + (size_t)(y - 3 + ry) * IMG_W + (x0 - 4);
            float4 a = *(const float4*)(p);
            float4 b = *(const float4*)(p + 4);
            float4 c = *(const float4*)(p + 8);
            r[ry][0] = a.x; r[ry][1] = a.y; r[ry][2]  = a.z; r[ry][3]  = a.w;
            r[ry][4] = b.x; r[ry][5] = b.y; r[ry][6]  = b.z; r[ry][7]  = b.w;
            r[ry][8] = c.x; r[ry][9] = c.y; r[ry][10] = c.z; r[ry][11] = c.w;
        }

        float4 res;
        float* resp = (float*)&res;
#pragma unroll
        for (int p = 0; p < 4; p++) {
            float center = r[3][4 + p];
            unsigned dark = 0u, bright = 0u;
#pragma unroll
            for (int i = 0; i < 16; i++) {
                float diff = r[3 + DY[i]][4 + p + DX[i]] - center;
                if (diff >=  THR) dark   |= (1u << i);
                if (diff <= -THR) bright |= (1u << i);
            }
            resp[p] = (run9(dark) || run9(bright)) ? 1.0f : 0.0f;
        }
        *(float4*)op = res;
    } else {
        // Border path: scalar loads with replicate-clamp.
#pragma unroll
        for (int p = 0; p < 4; p++) {
            int x = x0 + p;                 // W % 4 == 0, so x < IMG_W always
            float center = __ldg(im + (size_t)y * IMG_W + x);
            unsigned dark = 0u, bright = 0u;
#pragma unroll
            for (int i = 0; i < 16; i++) {
                int yy = min(max(y + DY[i], 0), IMG_H - 1);
                int xx = min(max(x + DX[i], 0), IMG_W - 1);
                float diff = __ldg(im + (size_t)yy * IMG_W + xx) - center;
                if (diff >=  THR) dark   |= (1u << i);
                if (diff <= -THR) bright |= (1u << i);
            }
            op[p] = (run9(dark) || run9(bright)) ? 1.0f : 0.0f;
        }
    }
}

extern "C" void kernel_launch(void* const* d_in, const int* in_sizes, int n_in,
                              void* d_out, int out_size)
{
    const float* img = (const float*)d_in[0];
    float* out = (float*)d_out;
    int N = in_sizes[0] / (IMG_H * IMG_W);

    dim3 block(128, 1, 1);
    // 1920 / 4 px-per-thread = 480 threads along x -> 4 blocks of 128
    dim3 grid((IMG_W / 4 + 127) / 128, IMG_H, N);
    fast_score_kernel<<<grid, block>>>(img, out, N);
}

// round 3
// speedup vs baseline: 1.3596x; 1.3596x over previous
#include <cuda_runtime.h>
#include <cuda_bf16.h>

#define IMG_H 1080
#define IMG_W 1920
#define THR 20.0f

// Run-of->=9 consecutive ones in a circular 16-bit mask.
// Shifts done as __umulhi (exact unsigned >>k) to run on the FMA pipe.
static __device__ __forceinline__ unsigned run9w(unsigned m16) {
    unsigned d = m16 * 0x10001u;                 // duplicate for circular wrap
    unsigned r = d & __umulhi(d, 0x80000000u);   // d >> 1  : runs >= 2
    r &= __umulhi(r, 0x40000000u);               // r >> 2  : runs >= 4
    r &= __umulhi(r, 0x10000000u);               // r >> 4  : runs >= 8
    r &= __umulhi(d, 0x01000000u);               // d >> 8  : runs >= 9
    return r & 0xFFFFu;
}

__global__ __launch_bounds__(128)
void fast_score_kernel(const float* __restrict__ img, float* __restrict__ out, int N)
{
    const int DY[16] = { 0, 1, 2, 3, 3, 3, 2, 1, 0, -1, -2, -3, -3, -3, -2, -1};
    const int DX[16] = {-3, -3, -2, -1, 0, 1, 2, 3, 3, 3, 2, 1, 0, -1, -2, -3};

    int x0 = (blockIdx.x * blockDim.x + threadIdx.x) * 4;
    int y  = blockIdx.y;
    int n  = blockIdx.z;
    if (x0 >= IMG_W) return;

    const float* im = img + (size_t)n * IMG_H * IMG_W;
    float*       op = out + ((size_t)n * IMG_H + y) * IMG_W + x0;

    bool interior = (y >= 3) & (y <= IMG_H - 4) & (x0 >= 4) & (x0 + 7 <= IMG_W - 1);

    if (interior) {
        // Row tiles, trimmed to the columns each row's circle samples need:
        // R0 (dy=-3): [x0-1 .. x0+4]  R1 (dy=-2): [x0-2 .. x0+5]
        // R2 (dy=-1): [x0-4 .. x0+7]  R3 (dy= 0): [x0-4 .. x0+7]
        // R4 (dy=+1): [x0-4 .. x0+7]  R5 (dy=+2): [x0-2 .. x0+5]
        // R6 (dy=+3): [x0-1 .. x0+4]
        float R0[6], R1[8], R2[12], R3[12], R4[12], R5[8], R6[6];
        {
            const float* p;
            p = im + (size_t)(y - 3) * IMG_W + x0;
            R0[0] = p[-1];
            { float4 v = *(const float4*)p; R0[1]=v.x; R0[2]=v.y; R0[3]=v.z; R0[4]=v.w; }
            R0[5] = p[4];
            p = im + (size_t)(y - 2) * IMG_W + x0;
            { float2 v = *(const float2*)(p - 2); R1[0]=v.x; R1[1]=v.y; }
            { float4 v = *(const float4*)p;       R1[2]=v.x; R1[3]=v.y; R1[4]=v.z; R1[5]=v.w; }
            { float2 v = *(const float2*)(p + 4); R1[6]=v.x; R1[7]=v.y; }
            p = im + (size_t)(y - 1) * IMG_W + (x0 - 4);
            { float4 a=*(const float4*)p, b=*(const float4*)(p+4), c=*(const float4*)(p+8);
              R2[0]=a.x;R2[1]=a.y;R2[2]=a.z;R2[3]=a.w;R2[4]=b.x;R2[5]=b.y;R2[6]=b.z;R2[7]=b.w;
              R2[8]=c.x;R2[9]=c.y;R2[10]=c.z;R2[11]=c.w; }
            p = im + (size_t)(y) * IMG_W + (x0 - 4);
            { float4 a=*(const float4*)p, b=*(const float4*)(p+4), c=*(const float4*)(p+8);
              R3[0]=a.x;R3[1]=a.y;R3[2]=a.z;R3[3]=a.w;R3[4]=b.x;R3[5]=b.y;R3[6]=b.z;R3[7]=b.w;
              R3[8]=c.x;R3[9]=c.y;R3[10]=c.z;R3[11]=c.w; }
            p = im + (size_t)(y + 1) * IMG_W + (x0 - 4);
            { float4 a=*(const float4*)p, b=*(const float4*)(p+4), c=*(const float4*)(p+8);
              R4[0]=a.x;R4[1]=a.y;R4[2]=a.z;R4[3]=a.w;R4[4]=b.x;R4[5]=b.y;R4[6]=b.z;R4[7]=b.w;
              R4[8]=c.x;R4[9]=c.y;R4[10]=c.z;R4[11]=c.w; }
            p = im + (size_t)(y + 2) * IMG_W + x0;
            { float2 v = *(const float2*)(p - 2); R5[0]=v.x; R5[1]=v.y; }
            { float4 v = *(const float4*)p;       R5[2]=v.x; R5[3]=v.y; R5[4]=v.z; R5[5]=v.w; }
            { float2 v = *(const float2*)(p + 4); R5[6]=v.x; R5[7]=v.y; }
            p = im + (size_t)(y + 3) * IMG_W + x0;
            R6[0] = p[-1];
            { float4 v = *(const float4*)p; R6[1]=v.x; R6[2]=v.y; R6[3]=v.z; R6[4]=v.w; }
            R6[5] = p[4];
        }

        float4 res;
        float* resp = (float*)&res;
#pragma unroll
        for (int p = 0; p < 4; p++) {
            float ctr = R3[p + 4];
            float d[16];
            d[0]  = R3[p + 1] - ctr;   // (0,-3)
            d[1]  = R4[p + 1] - ctr;   // (1,-3)
            d[2]  = R5[p + 0] - ctr;   // (2,-2)
            d[3]  = R6[p + 0] - ctr;   // (3,-1)
            d[4]  = R6[p + 1] - ctr;   // (3, 0)
            d[5]  = R6[p + 2] - ctr;   // (3, 1)
            d[6]  = R5[p + 4] - ctr;   // (2, 2)
            d[7]  = R4[p + 7] - ctr;   // (1, 3)
            d[8]  = R3[p + 7] - ctr;   // (0, 3)
            d[9]  = R2[p + 7] - ctr;   // (-1,3)
            d[10] = R1[p + 4] - ctr;   // (-2,2)
            d[11] = R0[p + 2] - ctr;   // (-3,1)
            d[12] = R0[p + 1] - ctr;   // (-3,0)
            d[13] = R0[p + 0] - ctr;   // (-3,-1)
            d[14] = R1[p + 0] - ctr;   // (-2,-2)
            d[15] = R2[p + 1] - ctr;   // (-1,-3)

            // Gather sign bits with funnel shifts: one SHF per bit.
            // nd bit i = (d[i] < 0);  ns bit i = (|d[i]| < 20)  [= NOT strong]
            unsigned nd = 0u, ns = 0u;
#pragma unroll
            for (int i = 15; i >= 0; i--) {
                float s = fabsf(d[i]) - THR;        // sign exact (Sterbenz @20)
                nd = __funnelshift_l(__float_as_uint(d[i]), nd, 1);
                ns = __funnelshift_l(__float_as_uint(s),    ns, 1);
            }

            unsigned dark   = ~ns & ~nd & 0xFFFFu;  // strong & (d >= 0)  [1 LOP3]
            unsigned bright = ~ns &  nd;            // strong & (d <  0)  [1 LOP3]

            unsigned det = run9w(dark) | run9w(bright);
            resp[p] = __uint_as_float(min(det, 1u) * 0x3F800000u);
        }
        *(float4*)op = res;
    } else {
        // Border path: scalar loads with replicate-clamp (rare; known-good R1 form).
#pragma unroll
        for (int p = 0; p < 4; p++) {
            int x = x0 + p;
            float center = __ldg(im + (size_t)y * IMG_W + x);
            unsigned dark = 0u, bright = 0u;
#pragma unroll
            for (int i = 0; i < 16; i++) {
                int yy = min(max(y + DY[i], 0), IMG_H - 1);
                int xx = min(max(x + DX[i], 0), IMG_W - 1);
                float diff = __ldg(im + (size_t)yy * IMG_W + xx) - center;
                if (diff >=  THR) dark   |= (1u << i);
                if (diff <= -THR) bright |= (1u << i);
            }
            unsigned det = run9w(dark) | run9w(bright);
            op[p] = __uint_as_float(min(det, 1u) * 0x3F800000u);
        }
    }
}

extern "C" void kernel_launch(void* const* d_in, const int* in_sizes, int n_in,
                              void* d_out, int out_size)
{
    const float* img = (const float*)d_in[0];
    float* out = (float*)d_out;
    int N = in_sizes[0] / (IMG_H * IMG_W);

    dim3 block(128, 1, 1);
    dim3 grid((IMG_W / 4 + 127) / 128, IMG_H, N);
    fast_score_kernel<<<grid, block>>>(img, out, N);
}

// round 4
// speedup vs baseline: 1.3615x; 1.0014x over previous
#include <cuda_runtime.h>
#include <cuda_bf16.h>

#define IMG_H 1080
#define IMG_W 1920
#define THR 20.0f

// Run-of->=9 consecutive ones in a circular 16-bit mask.
// Shifts done as __umulhi (exact unsigned >>k) to run on the FMA pipe.
static __device__ __forceinline__ unsigned run9w(unsigned m16) {
    unsigned d = m16 * 0x10001u;                 // duplicate for circular wrap
    unsigned r = d & __umulhi(d, 0x80000000u);   // d >> 1  : runs >= 2
    r &= __umulhi(r, 0x40000000u);               // r >> 2  : runs >= 4
    r &= __umulhi(r, 0x10000000u);               // r >> 4  : runs >= 8
    r &= __umulhi(d, 0x01000000u);               // d >> 8  : runs >= 9
    return r & 0xFFFFu;
}

__global__ __launch_bounds__(128)
void fast_score_kernel(const float* __restrict__ img, float* __restrict__ out, int N)
{
    const int DY[16] = { 0, 1, 2, 3, 3, 3, 2, 1, 0, -1, -2, -3, -3, -3, -2, -1};
    const int DX[16] = {-3, -3, -2, -1, 0, 1, 2, 3, 3, 3, 2, 1, 0, -1, -2, -3};

    int x0 = (blockIdx.x * blockDim.x + threadIdx.x) * 4;
    int y  = blockIdx.y;
    int n  = blockIdx.z;
    if (x0 >= IMG_W) return;

    const float* im = img + (size_t)n * IMG_H * IMG_W;
    float*       op = out + ((size_t)n * IMG_H + y) * IMG_W + x0;

    bool interior = (y >= 3) & (y <= IMG_H - 4) & (x0 >= 4) & (x0 + 7 <= IMG_W - 1);

    if (interior) {
        // Row tiles, trimmed to the columns each row's circle samples need:
        // R0 (dy=-3): [x0-1 .. x0+4]  R1 (dy=-2): [x0-2 .. x0+5]
        // R2 (dy=-1): [x0-4 .. x0+7]  R3 (dy= 0): [x0-4 .. x0+7]
        // R4 (dy=+1): [x0-4 .. x0+7]  R5 (dy=+2): [x0-2 .. x0+5]
        // R6 (dy=+3): [x0-1 .. x0+4]
        float R0[6], R1[8], R2[12], R3[12], R4[12], R5[8], R6[6];
        {
            const float* p;
            p = im + (size_t)(y - 3) * IMG_W + x0;
            R0[0] = p[-1];
            { float4 v = *(const float4*)p; R0[1]=v.x; R0[2]=v.y; R0[3]=v.z; R0[4]=v.w; }
            R0[5] = p[4];
            p = im + (size_t)(y - 2) * IMG_W + x0;
            { float2 v = *(const float2*)(p - 2); R1[0]=v.x; R1[1]=v.y; }
            { float4 v = *(const float4*)p;       R1[2]=v.x; R1[3]=v.y; R1[4]=v.z; R1[5]=v.w; }
            { float2 v = *(const float2*)(p + 4); R1[6]=v.x; R1[7]=v.y; }
            p = im + (size_t)(y - 1) * IMG_W + (x0 - 4);
            { float4 a=*(const float4*)p, b=*(const float4*)(p+4), c=*(const float4*)(p+8);
              R2[0]=a.x;R2[1]=a.y;R2[2]=a.z;R2[3]=a.w;R2[4]=b.x;R2[5]=b.y;R2[6]=b.z;R2[7]=b.w;
              R2[8]=c.x;R2[9]=c.y;R2[10]=c.z;R2[11]=c.w; }
            p = im + (size_t)(y) * IMG_W + (x0 - 4);
            { float4 a=*(const float4*)p, b=*(const float4*)(p+4), c=*(const float4*)(p+8);
              R3[0]=a.x;R3[1]=a.y;R3[2]=a.z;R3[3]=a.w;R3[4]=b.x;R3[5]=b.y;R3[6]=b.z;R3[7]=b.w;
              R3[8]=c.x;R3[9]=c.y;R3[10]=c.z;R3[11]=c.w; }
            p = im + (size_t)(y + 1) * IMG_W + (x0 - 4);
            { float4 a=*(const float4*)p, b=*(const float4*)(p+4), c=*(const float4*)(p+8);
              R4[0]=a.x;R4[1]=a.y;R4[2]=a.z;R4[3]=a.w;R4[4]=b.x;R4[5]=b.y;R4[6]=b.z;R4[7]=b.w;
              R4[8]=c.x;R4[9]=c.y;R4[10]=c.z;R4[11]=c.w; }
            p = im + (size_t)(y + 2) * IMG_W + x0;
            { float2 v = *(const float2*)(p - 2); R5[0]=v.x; R5[1]=v.y; }
            { float4 v = *(const float4*)p;       R5[2]=v.x; R5[3]=v.y; R5[4]=v.z; R5[5]=v.w; }
            { float2 v = *(const float2*)(p + 4); R5[6]=v.x; R5[7]=v.y; }
            p = im + (size_t)(y + 3) * IMG_W + x0;
            R6[0] = p[-1];
            { float4 v = *(const float4*)p; R6[1]=v.x; R6[2]=v.y; R6[3]=v.z; R6[4]=v.w; }
            R6[5] = p[4];
        }

        float4 res;
        float* resp = (float*)&res;
#pragma unroll
        for (int p = 0; p < 4; p++) {
            float ctr = R3[p + 4];
            float d[16];
            // diff via FFMA (c*1.0 - ctr): exact single-round == c - ctr,
            // runs on the FMA pipe (imm-multiplier FFMA, rt=1).
            d[0]  = __fmaf_rn(R3[p + 1], 1.0f, -ctr);   // (0,-3)
            d[1]  = __fmaf_rn(R4[p + 1], 1.0f, -ctr);   // (1,-3)
            d[2]  = __fmaf_rn(R5[p + 0], 1.0f, -ctr);   // (2,-2)
            d[3]  = __fmaf_rn(R6[p + 0], 1.0f, -ctr);   // (3,-1)
            d[4]  = __fmaf_rn(R6[p + 1], 1.0f, -ctr);   // (3, 0)
            d[5]  = __fmaf_rn(R6[p + 2], 1.0f, -ctr);   // (3, 1)
            d[6]  = __fmaf_rn(R5[p + 4], 1.0f, -ctr);   // (2, 2)
            d[7]  = __fmaf_rn(R4[p + 7], 1.0f, -ctr);   // (1, 3)
            d[8]  = __fmaf_rn(R3[p + 7], 1.0f, -ctr);   // (0, 3)
            d[9]  = __fmaf_rn(R2[p + 7], 1.0f, -ctr);   // (-1,3)
            d[10] = __fmaf_rn(R1[p + 4], 1.0f, -ctr);   // (-2,2)
            d[11] = __fmaf_rn(R0[p + 2], 1.0f, -ctr);   // (-3,1)
            d[12] = __fmaf_rn(R0[p + 1], 1.0f, -ctr);   // (-3,0)
            d[13] = __fmaf_rn(R0[p + 0], 1.0f, -ctr);   // (-3,-1)
            d[14] = __fmaf_rn(R1[p + 0], 1.0f, -ctr);   // (-2,-2)
            d[15] = __fmaf_rn(R2[p + 1], 1.0f, -ctr);   // (-1,-3)

            // Sign gathers: one SHF per bit (ALU pipe).
            // nd bit i = (d[i] < 0)
            // ns bit i = signbit(fma(d,d,-400)) = (d*d < 400) = (|d| < 20) [exact;
            //            |d|==20 -> +0 -> strong, matching the reference >= / <=]
            unsigned nd = 0u, ns = 0u;
#pragma unroll
            for (int i = 15; i >= 0; i--) {
                float s = __fmaf_rn(d[i], d[i], -400.0f);   // FMA pipe
                nd = __funnelshift_l(__float_as_uint(d[i]), nd, 1);
                ns = __funnelshift_l(__float_as_uint(s),    ns, 1);
            }

            unsigned dark   = ~ns & ~nd & 0xFFFFu;  // strong & (d >= 0)  [1 LOP3]
            unsigned bright = ~ns &  nd;            // strong & (d <  0)  [1 LOP3]

            unsigned det = run9w(dark) | run9w(bright);
            resp[p] = __uint_as_float(min(det, 1u) * 0x3F800000u);
        }
        *(float4*)op = res;
    } else {
        // Border path: scalar loads with replicate-clamp (rare; known-good form).
#pragma unroll
        for (int p = 0; p < 4; p++) {
            int x = x0 + p;
            float center = __ldg(im + (size_t)y * IMG_W + x);
            unsigned dark = 0u, bright = 0u;
#pragma unroll
            for (int i = 0; i < 16; i++) {
                int yy = min(max(y + DY[i], 0), IMG_H - 1);
                int xx = min(max(x + DX[i], 0), IMG_W - 1);
                float diff = __ldg(im + (size_t)yy * IMG_W + xx) - center;
                if (diff >=  THR) dark   |= (1u << i);
                if (diff <= -THR) bright |= (1u << i);
            }
            unsigned det = run9w(dark) | run9w(bright);
            op[p] = __uint_as_float(min(det, 1u) * 0x3F800000u);
        }
    }
}

extern "C" void kernel_launch(void* const* d_in, const int* in_sizes, int n_in,
                              void* d_out, int out_size)
{
    const float* img = (const float*)d_in[0];
    float* out = (float*)d_out;
    int N = in_sizes[0] / (IMG_H * IMG_W);

    dim3 block(128, 1, 1);
    dim3 grid((IMG_W / 4 + 127) / 128, IMG_H, N);
    fast_score_kernel<<<grid, block>>>(img, out, N);
}